// round 9
// baseline (speedup 1.0000x reference)
#include <cuda_runtime.h>
#include <cuda_bf16.h>
#include <math.h>
#include <cstdint>

#define NN   100000
#define NE   1600000
#define HD   64
#define NG   256
#define NLAY 3
#define G3   192   // 3*HD

#define SCAN_TPB  512
#define SCAN_BLKS ((NN + SCAN_TPB - 1) / SCAN_TPB)   // 196

// ---------------- scratch (device globals; no allocation allowed) -------------
__device__ float    g_h0[NN * HD];
__device__ float    g_h1[NN * HD];
__device__ uint32_t g_xb[NN * HD];     // packed (bf16hi | bf16lo<<16) of x
__device__ uint32_t g_h0b[NN * HD];    // packed h
__device__ uint32_t g_h1b[NN * HD];
__device__ uint32_t g_aggb[NN * HD];   // packed agg
__device__ int   g_rowptr[NN + 1];
__device__ int   g_cnt[NN];
__device__ int   g_aggv[SCAN_BLKS];
__device__ int   g_incv[SCAN_BLKS];
__device__ int   g_flag[SCAN_BLKS];
__device__ int   g_col[NE];
__device__ __nv_bfloat16 g_wfh[NLAY * G3 * HD];   // hi split of fused W@Wih^T, [l][gate][c]
__device__ __nv_bfloat16 g_wfl[NLAY * G3 * HD];   // lo split
__device__ __nv_bfloat16 g_whh_h[G3 * HD];
__device__ __nv_bfloat16 g_whh_l[G3 * HD];

// ---------------- ptx helpers (baseline ISA only: ldmatrix + mma.sync) --------
__device__ __forceinline__ uint32_t smem_u32(const void* p) {
    uint32_t a;
    asm("{ .reg .u64 t; cvta.to.shared.u64 t, %1; cvt.u32.u64 %0, t; }" : "=r"(a) : "l"(p));
    return a;
}
__device__ __forceinline__ void ldm4(uint32_t* r, uint32_t addr) {
    asm volatile("ldmatrix.sync.aligned.m8n8.x4.shared.b16 {%0,%1,%2,%3}, [%4];"
                 : "=r"(r[0]), "=r"(r[1]), "=r"(r[2]), "=r"(r[3]) : "r"(addr));
}
__device__ __forceinline__ void mma16816(float* d, const uint32_t* a, const uint32_t* b) {
    asm volatile(
        "mma.sync.aligned.m16n8k16.row.col.f32.bf16.bf16.f32 "
        "{%0,%1,%2,%3}, {%4,%5,%6,%7}, {%8,%9}, {%0,%1,%2,%3};"
        : "+f"(d[0]), "+f"(d[1]), "+f"(d[2]), "+f"(d[3])
        : "r"(a[0]), "r"(a[1]), "r"(a[2]), "r"(a[3]), "r"(b[0]), "r"(b[1]));
}
// packed split: low16 = bf16(v), high16 = bf16(v - hi)
__device__ __forceinline__ uint32_t packsplit(float v) {
    __nv_bfloat16 h = __float2bfloat16(v);
    float r = v - __bfloat162float(h);
    __nv_bfloat16 l = __float2bfloat16(r);
    return (uint32_t)(*(uint16_t*)&h) | ((uint32_t)(*(uint16_t*)&l) << 16);
}

// ---------------- prep: zero state + weight fusion + bf16 hi/lo split ---------
__global__ void prep_k(const float* __restrict__ W, const float* __restrict__ Wih,
                       const float* __restrict__ Whh, float* __restrict__ out) {
    int tid = blockIdx.x * blockDim.x + threadIdx.x;
    if (tid < NN) g_cnt[tid] = 0;
    if (tid < SCAN_BLKS) g_flag[tid] = 0;
    if (tid < NG * HD) out[tid] = 0.f;
    if (tid < NLAY * G3 * HD) {
        int c = tid & (HD - 1);
        int j = (tid >> 6) % G3;
        int l = tid / (G3 * HD);
        const float* wrow = W + (l * HD + c) * HD;
        const float* irow = Wih + j * HD;
        float s = 0.f;
#pragma unroll
        for (int k = 0; k < HD; k++) s = fmaf(wrow[k], irow[k], s);
        __nv_bfloat16 hi = __float2bfloat16(s);
        g_wfh[tid] = hi;
        g_wfl[tid] = __float2bfloat16(s - __bfloat162float(hi));
    }
    if (tid < G3 * HD) {
        float s = Whh[tid];
        __nv_bfloat16 hi = __float2bfloat16(s);
        g_whh_h[tid] = hi;
        g_whh_l[tid] = __float2bfloat16(s - __bfloat162float(hi));
    }
}

// one-shot: pack x into split-bf16 format for layer 0 staging
__global__ void pack_k(const float* __restrict__ x) {
    int i = blockIdx.x * blockDim.x + threadIdx.x;
    if (i < NN * HD) g_xb[i] = packsplit(x[i]);
}

// ---------------- CSR build ----------------------------------------------------
__global__ void hist_k(const int* __restrict__ dst) {
    int e = blockIdx.x * blockDim.x + threadIdx.x;
    if (e < NE) atomicAdd(&g_cnt[dst[e]], 1);
}

// single-pass decoupled-lookback scan (196 blocks, all resident)
__global__ void scan_k() {
    __shared__ int ss[SCAN_TPB];
    __shared__ int s_excl;
    int t = threadIdx.x, b = blockIdx.x;
    int i = b * SCAN_TPB + t;
    int orig = (i < NN) ? g_cnt[i] : 0;
    ss[t] = orig;
    __syncthreads();
#pragma unroll
    for (int off = 1; off < SCAN_TPB; off <<= 1) {
        int u = (t >= off) ? ss[t - off] : 0;
        __syncthreads();
        ss[t] += u;
        __syncthreads();
    }
    int incl = ss[t];
    int total = ss[SCAN_TPB - 1];

    if (t == 0) {
        if (b == 0) {
            *(volatile int*)&g_incv[0] = total;
            __threadfence();
            *(volatile int*)&g_flag[0] = 2;
            s_excl = 0;
        } else {
            *(volatile int*)&g_aggv[b] = total;
            __threadfence();
            *(volatile int*)&g_flag[b] = 1;
        }
    }
    if (b > 0 && t < 32) {
        int running = 0;
        for (int base = b - 1; base >= 0; base -= 32) {
            int idx = base - t;
            int f;
            do {
                f = (idx >= 0) ? *(volatile int*)&g_flag[idx] : 2;
            } while (__any_sync(0xffffffffu, f == 0));
            __threadfence();
            int val = 0;
            if (idx >= 0)
                val = (f == 2) ? *(volatile int*)&g_incv[idx] : *(volatile int*)&g_aggv[idx];
            unsigned m = __ballot_sync(0xffffffffu, (f == 2) && idx >= 0);
            int firstP = m ? (__ffs(m) - 1) : 32;
            int contrib = (t <= firstP && idx >= 0) ? val : 0;
#pragma unroll
            for (int o = 16; o; o >>= 1) contrib += __shfl_down_sync(0xffffffffu, contrib, o);
            contrib = __shfl_sync(0xffffffffu, contrib, 0);
            running += contrib;
            if (m) break;
        }
        if (t == 0) {
            *(volatile int*)&g_incv[b] = running + total;
            __threadfence();
            *(volatile int*)&g_flag[b] = 2;
            s_excl = running;
        }
    }
    __syncthreads();
    int excl = s_excl + incl - orig;
    if (i < NN) {
        g_rowptr[i] = excl;
        g_cnt[i] = excl;   // scatter cursor
    }
    if (i == 0) g_rowptr[NN] = NE;
}

__global__ void scatter_k(const int* __restrict__ src, const int* __restrict__ dst) {
    int e = blockIdx.x * blockDim.x + threadIdx.x;
    if (e < NE) {
        int p = atomicAdd(&g_cnt[dst[e]], 1);
        g_col[p] = src[e];
    }
}

// ---------------- aggregation: gather fp32 h, emit packed split-bf16 -----------
__global__ void agg_k(const float2* __restrict__ h2, uint2* __restrict__ outb) {
    int w    = (blockIdx.x * blockDim.x + threadIdx.x) >> 5;
    int lane = threadIdx.x & 31;
    if (w >= NN) return;
    int beg = g_rowptr[w], end = g_rowptr[w + 1];
    float2 acc = make_float2(0.f, 0.f);
    for (int base = beg; base < end; base += 32) {
        int m = min(32, end - base);
        int idx = 0;
        if (lane < m) idx = g_col[base + lane];
#pragma unroll 4
        for (int jj = 0; jj < m; jj++) {
            int s = __shfl_sync(0xffffffffu, idx, jj);
            float2 v = h2[s * 32 + lane];
            acc.x += v.x;
            acc.y += v.y;
        }
    }
    outb[w * 32 + lane] = make_uint2(packsplit(acc.x), packsplit(acc.y));
}

// ---------------- GRU via mma.sync bf16 split: packed staging, reg epilogue ----
#define ROWB 144
#define OFF_AH 0
#define OFF_AL 9216
#define OFF_HH 18432
#define OFF_HL 27648
#define OFF_FH 36864
#define OFF_FL 64512
#define OFF_GH 92160
#define OFF_GL 119808
#define GRU_SMEM 147456
#define NTILES ((NN + 63) / 64)   // 1563
#define GRU_GRID 148
#define GRU_TPB 256

#define IDX(p, t, h) ((((p) * 2 + (t)) * 2 + (h)) * 4)

__global__ void __launch_bounds__(GRU_TPB, 1) gru_mma(
    const uint32_t* __restrict__ aggb, const uint32_t* __restrict__ hinb,
    float* __restrict__ hout, uint32_t* __restrict__ houtb,
    const __nv_bfloat16* __restrict__ wfh, const __nv_bfloat16* __restrict__ wfl,
    const float* __restrict__ bih, const float* __restrict__ bhh) {
    extern __shared__ __align__(16) char sm[];
    int tid = threadIdx.x, wid = tid >> 5, lane = tid & 31;

    // ---- stage weights ONCE (bf16, [gate][c] rows) ----
    for (int i = tid; i < G3 * 16; i += GRU_TPB) {
        int r = i >> 4, c8 = i & 15;
        uint32_t off = r * ROWB + c8 * 8;
        *(uint2*)(sm + OFF_FH + off) = *(const uint2*)(wfh + r * 64 + c8 * 4);
        *(uint2*)(sm + OFF_FL + off) = *(const uint2*)(wfl + r * 64 + c8 * 4);
        *(uint2*)(sm + OFF_GH + off) = *(const uint2*)(g_whh_h + r * 64 + c8 * 4);
        *(uint2*)(sm + OFF_GL + off) = *(const uint2*)(g_whh_l + r * 64 + c8 * 4);
    }

    uint32_t sbase = smem_u32(sm);
    int mrow0 = (wid & 3) * 16;        // 4 M-stripes of 16 rows
    int d0 = (wid >> 2) * 32;          // 2 feature groups of 32
    uint32_t aOff = (mrow0 + (lane & 15)) * ROWB + (lane >> 4) * 16;
    uint32_t bRow = (lane >> 4) * 8 + (lane & 7);
    uint32_t bCol = ((lane >> 3) & 1) * 16;

    // per-thread bias preload
    float brz[8], bz[8], bin_[8], bhn[8];
#pragma unroll
    for (int t = 0; t < 2; t++)
#pragma unroll
        for (int h = 0; h < 2; h++)
#pragma unroll
            for (int j = 0; j < 2; j++) {
                int m = (t * 2 + h) * 2 + j;
                int d = d0 + t * 16 + h * 8 + (lane & 3) * 2 + j;
                brz[m]  = __ldg(bih + d) + __ldg(bhh + d);
                bz[m]   = __ldg(bih + 64 + d) + __ldg(bhh + 64 + d);
                bin_[m] = __ldg(bih + 128 + d);
                bhn[m]  = __ldg(bhh + 128 + d);
            }

    for (int tile = blockIdx.x; tile < NTILES; tile += GRU_GRID) {
        int n0 = tile * 64;
        __syncthreads();   // staging region reuse vs previous tile's readers

        // ---- stage A/H from packed split (PRMT only, no cvt) ----
        for (int i = tid; i < 64 * 16; i += GRU_TPB) {
            int t = i >> 4, c4 = i & 15;
            uint4 pa = make_uint4(0u, 0u, 0u, 0u), ph = pa;
            if (n0 + t < NN) {
                pa = ((const uint4*)(aggb + (size_t)(n0 + t) * HD))[c4];
                ph = ((const uint4*)(hinb + (size_t)(n0 + t) * HD))[c4];
            }
            uint32_t off = t * ROWB + c4 * 8;
            *(uint2*)(sm + OFF_AH + off) =
                make_uint2(__byte_perm(pa.x, pa.y, 0x5410), __byte_perm(pa.z, pa.w, 0x5410));
            *(uint2*)(sm + OFF_AL + off) =
                make_uint2(__byte_perm(pa.x, pa.y, 0x7632), __byte_perm(pa.z, pa.w, 0x7632));
            *(uint2*)(sm + OFF_HH + off) =
                make_uint2(__byte_perm(ph.x, ph.y, 0x5410), __byte_perm(ph.z, ph.w, 0x5410));
            *(uint2*)(sm + OFF_HL + off) =
                make_uint2(__byte_perm(ph.x, ph.y, 0x7632), __byte_perm(ph.z, ph.w, 0x7632));
        }
        __syncthreads();

        // ---- GEMMs: 3 gate planes x 2 n16 groups per warp ----
        float dgi[48], dgh[48];
#pragma unroll
        for (int q = 0; q < 48; q++) { dgi[q] = 0.f; dgh[q] = 0.f; }

#pragma unroll
        for (int ks = 0; ks < 4; ks++) {
            uint32_t kb = ks * 32;
            uint32_t aH[4], aL[4], hH[4], hL[4];
            ldm4(aH, sbase + OFF_AH + aOff + kb);
            ldm4(aL, sbase + OFF_AL + aOff + kb);
            ldm4(hH, sbase + OFF_HH + aOff + kb);
            ldm4(hL, sbase + OFF_HL + aOff + kb);
#pragma unroll
            for (int p = 0; p < 3; p++) {
#pragma unroll
                for (int t = 0; t < 2; t++) {
                    uint32_t bo = (p * 64 + d0 + t * 16 + bRow) * ROWB + bCol + kb;
                    int I = IDX(p, t, 0);
                    uint32_t bFH[4], bGH[4];
                    ldm4(bFH, sbase + OFF_FH + bo);
                    ldm4(bGH, sbase + OFF_GH + bo);
                    mma16816(dgi + I,     aH, bFH);
                    mma16816(dgi + I + 4, aH, bFH + 2);
                    mma16816(dgi + I,     aL, bFH);
                    mma16816(dgi + I + 4, aL, bFH + 2);
                    mma16816(dgh + I,     hH, bGH);
                    mma16816(dgh + I + 4, hH, bGH + 2);
                    mma16816(dgh + I,     hL, bGH);
                    mma16816(dgh + I + 4, hL, bGH + 2);
                    uint32_t bFL[4], bGL[4];
                    ldm4(bFL, sbase + OFF_FL + bo);
                    ldm4(bGL, sbase + OFF_GL + bo);
                    mma16816(dgi + I,     aH, bFL);
                    mma16816(dgi + I + 4, aH, bFL + 2);
                    mma16816(dgh + I,     hH, bGL);
                    mma16816(dgh + I + 4, hH, bGL + 2);
                }
            }
        }

        // ---- register epilogue: r/z/n in this thread's accumulators ----
#pragma unroll
        for (int t = 0; t < 2; t++)
#pragma unroll
            for (int h = 0; h < 2; h++) {
                int dE = d0 + t * 16 + h * 8 + (lane & 3) * 2;
#pragma unroll
                for (int rh = 0; rh < 2; rh++) {
                    int row = mrow0 + (lane >> 2) + rh * 8;
                    if (n0 + row >= NN) continue;
                    uint32_t o = row * ROWB + dE * 2;
                    __nv_bfloat162 p2h = *(const __nv_bfloat162*)(sm + OFF_HH + o);
                    __nv_bfloat162 p2l = *(const __nv_bfloat162*)(sm + OFF_HL + o);
                    float hp[2] = {__bfloat162float(p2h.x) + __bfloat162float(p2l.x),
                                   __bfloat162float(p2h.y) + __bfloat162float(p2l.y)};
                    float outv[2];
#pragma unroll
                    for (int j = 0; j < 2; j++) {
                        int q = rh * 2 + j;
                        int m = (t * 2 + h) * 2 + j;
                        float ar = dgi[IDX(0, t, h) + q] + dgh[IDX(0, t, h) + q] + brz[m];
                        float az = dgi[IDX(1, t, h) + q] + dgh[IDX(1, t, h) + q] + bz[m];
                        float r = 1.f / (1.f + __expf(-ar));
                        float z = 1.f / (1.f + __expf(-az));
                        float xarg = dgi[IDX(2, t, h) + q] + bin_[m] +
                                     r * (dgh[IDX(2, t, h) + q] + bhn[m]);
                        float nn = 1.f - 2.f / (__expf(2.f * xarg) + 1.f);  // tanh
                        outv[j] = (1.f - z) * nn + z * hp[j];
                    }
                    size_t gidx = (size_t)(n0 + row) * HD + dE;
                    *(float2*)(hout + gidx) = make_float2(outv[0], outv[1]);
                    *(uint2*)(houtb + gidx) =
                        make_uint2(packsplit(outv[0]), packsplit(outv[1]));
                }
            }
    }
}

// ---------------- pooling: batch sorted -> run-length accumulate ---------------
__global__ void pool_k(const float* __restrict__ h, const int* __restrict__ batch,
                       float* __restrict__ out) {
    int d = threadIdx.x;
    int n0 = blockIdx.x * 128;
    int nend = min(n0 + 128, NN);
    if (n0 >= NN) return;
    float acc = 0.f;
    int cur = batch[n0];
    for (int n = n0; n < nend; n++) {
        int b = batch[n];
        if (b != cur) {
            atomicAdd(&out[cur * HD + d], acc);
            acc = 0.f;
            cur = b;
        }
        acc += h[(size_t)n * HD + d];
    }
    atomicAdd(&out[cur * HD + d], acc);
}

// ---------------- launch --------------------------------------------------------
extern "C" void kernel_launch(void* const* d_in, const int* in_sizes, int n_in,
                              void* d_out, int out_size) {
    const float* x    = (const float*)d_in[0];
    const int*   ei   = (const int*)d_in[1];
    const int*   batch= (const int*)d_in[2];
    const float* W    = (const float*)d_in[3];
    const float* Wih  = (const float*)d_in[4];
    const float* Whh  = (const float*)d_in[5];
    const float* bih  = (const float*)d_in[6];
    const float* bhh  = (const float*)d_in[7];
    float* out = (float*)d_out;
    const int* src = ei;
    const int* dst = ei + NE;

    void *h0p, *h1p, *xbp, *h0bp, *h1bp, *aggbp, *wfhp, *wflp;
    cudaGetSymbolAddress(&h0p, g_h0);
    cudaGetSymbolAddress(&h1p, g_h1);
    cudaGetSymbolAddress(&xbp, g_xb);
    cudaGetSymbolAddress(&h0bp, g_h0b);
    cudaGetSymbolAddress(&h1bp, g_h1b);
    cudaGetSymbolAddress(&aggbp, g_aggb);
    cudaGetSymbolAddress(&wfhp, g_wfh);
    cudaGetSymbolAddress(&wflp, g_wfl);

    cudaFuncSetAttribute(gru_mma, cudaFuncAttributeMaxDynamicSharedMemorySize, GRU_SMEM);

    prep_k<<<(NN + 255) / 256, 256>>>(W, Wih, Whh, out);
    pack_k<<<(NN * HD + 255) / 256, 256>>>(x);
    hist_k<<<(NE + 255) / 256, 256>>>(dst);
    scan_k<<<SCAN_BLKS, SCAN_TPB>>>();
    scatter_k<<<(NE + 255) / 256, 256>>>(src, dst);

    const float*    hin  = x;
    const uint32_t* hinb = (const uint32_t*)xbp;
    for (int l = 0; l < NLAY; l++) {
        float*    hout  = (l & 1) ? (float*)h0p : (float*)h1p;
        uint32_t* houtb = (l & 1) ? (uint32_t*)h0bp : (uint32_t*)h1bp;
        agg_k<<<(NN * 32) / 256, 256>>>((const float2*)hin, (uint2*)aggbp);
        gru_mma<<<GRU_GRID, GRU_TPB, GRU_SMEM>>>(
            (const uint32_t*)aggbp, hinb, hout, houtb,
            (const __nv_bfloat16*)wfhp + (size_t)l * G3 * HD,
            (const __nv_bfloat16*)wflp + (size_t)l * G3 * HD,
            bih, bhh);
        hin = hout;
        hinb = houtb;
    }
    pool_k<<<(NN + 127) / 128, 64>>>(hin, batch, out);
}

// round 10
// speedup vs baseline: 1.4000x; 1.4000x over previous
#include <cuda_runtime.h>
#include <cuda_fp16.h>
#include <math.h>
#include <cstdint>

#define NN   100000
#define NE   1600000
#define HD   64
#define NG   256
#define NLAY 3
#define G3   192   // 3*HD

#define SCAN_TPB  512
#define SCAN_BLKS ((NN + SCAN_TPB - 1) / SCAN_TPB)   // 196

// ---------------- scratch (device globals; no allocation allowed) -------------
__device__ float g_h0[NN * HD];
__device__ float g_h1[NN * HD];
__device__ float g_agg[NN * HD];
__device__ int   g_rowptr[NN + 1];
__device__ int   g_cnt[NN];
__device__ int   g_aggv[SCAN_BLKS];
__device__ int   g_incv[SCAN_BLKS];
__device__ int   g_flag[SCAN_BLKS];
__device__ int   g_col[NE];
__device__ __half g_wf[NLAY * G3 * HD];   // fp16 fused W@Wih^T, [l][gate][c]
__device__ __half g_wh[G3 * HD];          // fp16 W_hh

// ---------------- ptx helpers (baseline ISA only: ldmatrix + mma.sync) --------
__device__ __forceinline__ uint32_t smem_u32(const void* p) {
    uint32_t a;
    asm("{ .reg .u64 t; cvta.to.shared.u64 t, %1; cvt.u32.u64 %0, t; }" : "=r"(a) : "l"(p));
    return a;
}
__device__ __forceinline__ void ldm4(uint32_t* r, uint32_t addr) {
    asm volatile("ldmatrix.sync.aligned.m8n8.x4.shared.b16 {%0,%1,%2,%3}, [%4];"
                 : "=r"(r[0]), "=r"(r[1]), "=r"(r[2]), "=r"(r[3]) : "r"(addr));
}
__device__ __forceinline__ void mma16816(float* d, const uint32_t* a, const uint32_t* b) {
    asm volatile(
        "mma.sync.aligned.m16n8k16.row.col.f32.f16.f16.f32 "
        "{%0,%1,%2,%3}, {%4,%5,%6,%7}, {%8,%9}, {%0,%1,%2,%3};"
        : "+f"(d[0]), "+f"(d[1]), "+f"(d[2]), "+f"(d[3])
        : "r"(a[0]), "r"(a[1]), "r"(a[2]), "r"(a[3]), "r"(b[0]), "r"(b[1]));
}
__device__ __forceinline__ uint32_t pack_h2(float a, float b) {
    __half2 t = __floats2half2_rn(a, b);
    return *(uint32_t*)&t;
}

// ---------------- prep: zero state + weight fusion + fp16 cast -----------------
__global__ void prep_k(const float* __restrict__ W, const float* __restrict__ Wih,
                       const float* __restrict__ Whh, float* __restrict__ out) {
    int tid = blockIdx.x * blockDim.x + threadIdx.x;
    if (tid < NN) g_cnt[tid] = 0;
    if (tid < SCAN_BLKS) g_flag[tid] = 0;
    if (tid < NG * HD) out[tid] = 0.f;
    if (tid < NLAY * G3 * HD) {
        int c = tid & (HD - 1);
        int j = (tid >> 6) % G3;
        int l = tid / (G3 * HD);
        const float* wrow = W + (l * HD + c) * HD;
        const float* irow = Wih + j * HD;
        float s = 0.f;
#pragma unroll
        for (int k = 0; k < HD; k++) s = fmaf(wrow[k], irow[k], s);
        g_wf[tid] = __float2half(s);
    }
    if (tid < G3 * HD) g_wh[tid] = __float2half(Whh[tid]);
}

// ---------------- CSR build ----------------------------------------------------
__global__ void hist_k(const int* __restrict__ dst) {
    int e = blockIdx.x * blockDim.x + threadIdx.x;
    if (e < NE) atomicAdd(&g_cnt[dst[e]], 1);
}

// single-pass decoupled-lookback scan (196 blocks, all resident)
__global__ void scan_k() {
    __shared__ int ss[SCAN_TPB];
    __shared__ int s_excl;
    int t = threadIdx.x, b = blockIdx.x;
    int i = b * SCAN_TPB + t;
    int orig = (i < NN) ? g_cnt[i] : 0;
    ss[t] = orig;
    __syncthreads();
#pragma unroll
    for (int off = 1; off < SCAN_TPB; off <<= 1) {
        int u = (t >= off) ? ss[t - off] : 0;
        __syncthreads();
        ss[t] += u;
        __syncthreads();
    }
    int incl = ss[t];
    int total = ss[SCAN_TPB - 1];

    if (t == 0) {
        if (b == 0) {
            *(volatile int*)&g_incv[0] = total;
            __threadfence();
            *(volatile int*)&g_flag[0] = 2;
            s_excl = 0;
        } else {
            *(volatile int*)&g_aggv[b] = total;
            __threadfence();
            *(volatile int*)&g_flag[b] = 1;
        }
    }
    if (b > 0 && t < 32) {
        int running = 0;
        for (int base = b - 1; base >= 0; base -= 32) {
            int idx = base - t;
            int f;
            do {
                f = (idx >= 0) ? *(volatile int*)&g_flag[idx] : 2;
            } while (__any_sync(0xffffffffu, f == 0));
            __threadfence();
            int val = 0;
            if (idx >= 0)
                val = (f == 2) ? *(volatile int*)&g_incv[idx] : *(volatile int*)&g_aggv[idx];
            unsigned m = __ballot_sync(0xffffffffu, (f == 2) && idx >= 0);
            int firstP = m ? (__ffs(m) - 1) : 32;
            int contrib = (t <= firstP && idx >= 0) ? val : 0;
#pragma unroll
            for (int o = 16; o; o >>= 1) contrib += __shfl_down_sync(0xffffffffu, contrib, o);
            contrib = __shfl_sync(0xffffffffu, contrib, 0);
            running += contrib;
            if (m) break;
        }
        if (t == 0) {
            *(volatile int*)&g_incv[b] = running + total;
            __threadfence();
            *(volatile int*)&g_flag[b] = 2;
            s_excl = running;
        }
    }
    __syncthreads();
    int excl = s_excl + incl - orig;
    if (i < NN) {
        g_rowptr[i] = excl;
        g_cnt[i] = excl;   // scatter cursor
    }
    if (i == 0) g_rowptr[NN] = NE;
}

__global__ void scatter_k(const int* __restrict__ src, const int* __restrict__ dst) {
    int e = blockIdx.x * blockDim.x + threadIdx.x;
    if (e < NE) {
        int p = atomicAdd(&g_cnt[dst[e]], 1);
        g_col[p] = src[e];
    }
}

// ---------------- aggregation: one warp per node, float2 per lane --------------
__global__ void agg_k(const float2* __restrict__ h2, float2* __restrict__ out2) {
    int w    = (blockIdx.x * blockDim.x + threadIdx.x) >> 5;
    int lane = threadIdx.x & 31;
    if (w >= NN) return;
    int beg = g_rowptr[w], end = g_rowptr[w + 1];
    float2 acc = make_float2(0.f, 0.f);
    for (int base = beg; base < end; base += 32) {
        int m = min(32, end - base);
        int idx = 0;
        if (lane < m) idx = g_col[base + lane];
#pragma unroll 4
        for (int jj = 0; jj < m; jj++) {
            int s = __shfl_sync(0xffffffffu, idx, jj);
            float2 v = h2[s * 32 + lane];
            acc.x += v.x;
            acc.y += v.y;
        }
    }
    out2[w * 32 + lane] = acc;
}

// ---------------- GRU via single-product fp16 mma.sync, reg epilogue -----------
// SMEM: A 9216 + H 9216 + Wf 27648 + Wh 27648 = 73728 bytes
#define ROWB 144
#define OFF_A  0
#define OFF_H  9216
#define OFF_WF 18432
#define OFF_WH 46080
#define GRU_SMEM 73728
#define NTILES ((NN + 63) / 64)   // 1563
#define GRU_GRID 148
#define GRU_TPB 256

#define IDX(p, t, h) ((((p) * 2 + (t)) * 2 + (h)) * 4)

__global__ void __launch_bounds__(GRU_TPB, 1) gru_mma(
    const float* __restrict__ agg, const float* __restrict__ hin,
    float* __restrict__ hout,
    const __half* __restrict__ wf,
    const float* __restrict__ bih, const float* __restrict__ bhh) {
    extern __shared__ __align__(16) char sm[];
    int tid = threadIdx.x, wid = tid >> 5, lane = tid & 31;

    // ---- stage weights ONCE (fp16, [gate][c] rows) ----
    for (int i = tid; i < G3 * 16; i += GRU_TPB) {
        int r = i >> 4, c8 = i & 15;
        uint32_t off = r * ROWB + c8 * 8;
        *(uint2*)(sm + OFF_WF + off) = *(const uint2*)(wf + r * 64 + c8 * 4);
        *(uint2*)(sm + OFF_WH + off) = *(const uint2*)(g_wh + r * 64 + c8 * 4);
    }

    uint32_t sbase = smem_u32(sm);
    int mrow0 = (wid & 3) * 16;        // 4 M-stripes of 16 rows
    int d0 = (wid >> 2) * 32;          // 2 feature groups of 32
    uint32_t aOff = (mrow0 + (lane & 15)) * ROWB + (lane >> 4) * 16;
    uint32_t bRow = (lane >> 4) * 8 + (lane & 7);
    uint32_t bCol = ((lane >> 3) & 1) * 16;

    // per-thread bias preload
    float brz[8], bz[8], bin_[8], bhn[8];
#pragma unroll
    for (int t = 0; t < 2; t++)
#pragma unroll
        for (int h = 0; h < 2; h++)
#pragma unroll
            for (int j = 0; j < 2; j++) {
                int m = (t * 2 + h) * 2 + j;
                int d = d0 + t * 16 + h * 8 + (lane & 3) * 2 + j;
                brz[m]  = __ldg(bih + d) + __ldg(bhh + d);
                bz[m]   = __ldg(bih + 64 + d) + __ldg(bhh + 64 + d);
                bin_[m] = __ldg(bih + 128 + d);
                bhn[m]  = __ldg(bhh + 128 + d);
            }

    // ---- register prefetch pipeline for A/H tiles ----
    float4 pa[4], ph[4];
    {
        int n0p = blockIdx.x * 64;
#pragma unroll
        for (int k = 0; k < 4; k++) {
            int i = tid + k * GRU_TPB;
            int t = i >> 4, c4 = i & 15;
            pa[k] = make_float4(0.f, 0.f, 0.f, 0.f);
            ph[k] = pa[k];
            if (n0p + t < NN) {
                pa[k] = ((const float4*)(agg + (size_t)(n0p + t) * HD))[c4];
                ph[k] = ((const float4*)(hin + (size_t)(n0p + t) * HD))[c4];
            }
        }
    }

    for (int tile = blockIdx.x; tile < NTILES; tile += GRU_GRID) {
        int n0 = tile * 64;

        // ---- prefetch h_prev (fp32, global) for this tile's epilogue ----
        float2 hp[8];
#pragma unroll
        for (int t = 0; t < 2; t++)
#pragma unroll
            for (int h = 0; h < 2; h++)
#pragma unroll
                for (int rh = 0; rh < 2; rh++) {
                    int q = (t * 2 + h) * 2 + rh;
                    int row = mrow0 + (lane >> 2) + rh * 8;
                    int dE = d0 + t * 16 + h * 8 + (lane & 3) * 2;
                    hp[q] = make_float2(0.f, 0.f);
                    if (n0 + row < NN)
                        hp[q] = *(const float2*)(hin + (size_t)(n0 + row) * HD + dE);
                }

        __syncthreads();   // previous tile's MMA readers done

        // ---- stage A/H from prefetched registers (fp32 -> fp16) ----
#pragma unroll
        for (int k = 0; k < 4; k++) {
            int i = tid + k * GRU_TPB;
            int t = i >> 4, c4 = i & 15;
            uint32_t off = t * ROWB + c4 * 8;
            *(uint2*)(sm + OFF_A + off) =
                make_uint2(pack_h2(pa[k].x, pa[k].y), pack_h2(pa[k].z, pa[k].w));
            *(uint2*)(sm + OFF_H + off) =
                make_uint2(pack_h2(ph[k].x, ph[k].y), pack_h2(ph[k].z, ph[k].w));
        }
        __syncthreads();

        // ---- issue next tile's global loads (overlap with MMA below) ----
        if (tile + GRU_GRID < NTILES) {
            int n0p = (tile + GRU_GRID) * 64;
#pragma unroll
            for (int k = 0; k < 4; k++) {
                int i = tid + k * GRU_TPB;
                int t = i >> 4, c4 = i & 15;
                if (n0p + t < NN) {
                    pa[k] = ((const float4*)(agg + (size_t)(n0p + t) * HD))[c4];
                    ph[k] = ((const float4*)(hin + (size_t)(n0p + t) * HD))[c4];
                } else {
                    pa[k] = make_float4(0.f, 0.f, 0.f, 0.f);
                    ph[k] = pa[k];
                }
            }
        }

        // ---- single-product fp16 GEMMs: 3 gate planes x 2 n16 groups ----
        float dgi[48], dgh[48];
#pragma unroll
        for (int q = 0; q < 48; q++) { dgi[q] = 0.f; dgh[q] = 0.f; }

#pragma unroll
        for (int ks = 0; ks < 4; ks++) {
            uint32_t kb = ks * 32;
            uint32_t aF[4], hF[4];
            ldm4(aF, sbase + OFF_A + aOff + kb);
            ldm4(hF, sbase + OFF_H + aOff + kb);
#pragma unroll
            for (int p = 0; p < 3; p++) {
#pragma unroll
                for (int t = 0; t < 2; t++) {
                    uint32_t bo = (p * 64 + d0 + t * 16 + bRow) * ROWB + bCol + kb;
                    int I = IDX(p, t, 0);
                    uint32_t bF[4], bG[4];
                    ldm4(bF, sbase + OFF_WF + bo);
                    ldm4(bG, sbase + OFF_WH + bo);
                    mma16816(dgi + I,     aF, bF);
                    mma16816(dgi + I + 4, aF, bF + 2);
                    mma16816(dgh + I,     hF, bG);
                    mma16816(dgh + I + 4, hF, bG + 2);
                }
            }
        }

        // ---- register epilogue: r/z/n in this thread's accumulators ----
#pragma unroll
        for (int t = 0; t < 2; t++)
#pragma unroll
            for (int h = 0; h < 2; h++) {
                int dE = d0 + t * 16 + h * 8 + (lane & 3) * 2;
#pragma unroll
                for (int rh = 0; rh < 2; rh++) {
                    int row = mrow0 + (lane >> 2) + rh * 8;
                    if (n0 + row >= NN) continue;
                    float2 hpv = hp[(t * 2 + h) * 2 + rh];
                    float hpa[2] = {hpv.x, hpv.y};
                    float outv[2];
#pragma unroll
                    for (int j = 0; j < 2; j++) {
                        int q = rh * 2 + j;
                        int m = (t * 2 + h) * 2 + j;
                        float ar = dgi[IDX(0, t, h) + q] + dgh[IDX(0, t, h) + q] + brz[m];
                        float az = dgi[IDX(1, t, h) + q] + dgh[IDX(1, t, h) + q] + bz[m];
                        float r = 1.f / (1.f + __expf(-ar));
                        float z = 1.f / (1.f + __expf(-az));
                        float xarg = dgi[IDX(2, t, h) + q] + bin_[m] +
                                     r * (dgh[IDX(2, t, h) + q] + bhn[m]);
                        float nn = 1.f - 2.f / (__expf(2.f * xarg) + 1.f);  // tanh
                        outv[j] = (1.f - z) * nn + z * hpa[j];
                    }
                    *(float2*)(hout + (size_t)(n0 + row) * HD + dE) =
                        make_float2(outv[0], outv[1]);
                }
            }
    }
}

// ---------------- pooling: batch sorted -> run-length accumulate ---------------
__global__ void pool_k(const float* __restrict__ h, const int* __restrict__ batch,
                       float* __restrict__ out) {
    int d = threadIdx.x;
    int n0 = blockIdx.x * 128;
    int nend = min(n0 + 128, NN);
    if (n0 >= NN) return;
    float acc = 0.f;
    int cur = batch[n0];
    for (int n = n0; n < nend; n++) {
        int b = batch[n];
        if (b != cur) {
            atomicAdd(&out[cur * HD + d], acc);
            acc = 0.f;
            cur = b;
        }
        acc += h[(size_t)n * HD + d];
    }
    atomicAdd(&out[cur * HD + d], acc);
}

// ---------------- launch --------------------------------------------------------
extern "C" void kernel_launch(void* const* d_in, const int* in_sizes, int n_in,
                              void* d_out, int out_size) {
    const float* x    = (const float*)d_in[0];
    const int*   ei   = (const int*)d_in[1];
    const int*   batch= (const int*)d_in[2];
    const float* W    = (const float*)d_in[3];
    const float* Wih  = (const float*)d_in[4];
    const float* Whh  = (const float*)d_in[5];
    const float* bih  = (const float*)d_in[6];
    const float* bhh  = (const float*)d_in[7];
    float* out = (float*)d_out;
    const int* src = ei;
    const int* dst = ei + NE;

    void *h0p, *h1p, *aggp, *wfp;
    cudaGetSymbolAddress(&h0p, g_h0);
    cudaGetSymbolAddress(&h1p, g_h1);
    cudaGetSymbolAddress(&aggp, g_agg);
    cudaGetSymbolAddress(&wfp, g_wf);

    cudaFuncSetAttribute(gru_mma, cudaFuncAttributeMaxDynamicSharedMemorySize, GRU_SMEM);

    prep_k<<<(NN + 255) / 256, 256>>>(W, Wih, Whh, out);
    hist_k<<<(NE + 255) / 256, 256>>>(dst);
    scan_k<<<SCAN_BLKS, SCAN_TPB>>>();
    scatter_k<<<(NE + 255) / 256, 256>>>(src, dst);

    const float* hin = x;
    for (int l = 0; l < NLAY; l++) {
        float* hout = (l & 1) ? (float*)h0p : (float*)h1p;
        agg_k<<<(NN * 32) / 256, 256>>>((const float2*)hin, (float2*)aggp);
        gru_mma<<<GRU_GRID, GRU_TPB, GRU_SMEM>>>(
            (const float*)aggp, hin, hout,
            (const __half*)wfp + (size_t)l * G3 * HD,
            bih, bhh);
        hin = hout;
    }
    pool_k<<<(NN + 127) / 128, 64>>>(hin, batch, out);
}

// round 11
// speedup vs baseline: 1.5212x; 1.0865x over previous
#include <cuda_runtime.h>
#include <cuda_fp16.h>
#include <math.h>
#include <cstdint>

#define NN   100000
#define NE   1600000
#define HD   64
#define NG   256
#define NLAY 3
#define G3   192   // 3*HD

#define SCAN_TPB  512
#define SCAN_BLKS ((NN + SCAN_TPB - 1) / SCAN_TPB)   // 196

// ---------------- scratch (device globals; no allocation allowed) -------------
__device__ float g_h0[NN * HD];
__device__ float g_h1[NN * HD];
__device__ float g_agg[NN * HD];
__device__ int   g_rowptr[NN + 1];
__device__ int   g_cnt[NN];
__device__ int   g_aggv[SCAN_BLKS];
__device__ int   g_incv[SCAN_BLKS];
__device__ int   g_flag[SCAN_BLKS];
__device__ int   g_col[NE];
__device__ __half g_wf[NLAY * G3 * HD];   // fp16 fused W@Wih^T, [l][gate][c]
__device__ __half g_wh[G3 * HD];          // fp16 W_hh

// ---------------- ptx helpers (baseline ISA only: ldmatrix + mma.sync) --------
__device__ __forceinline__ uint32_t smem_u32(const void* p) {
    uint32_t a;
    asm("{ .reg .u64 t; cvta.to.shared.u64 t, %1; cvt.u32.u64 %0, t; }" : "=r"(a) : "l"(p));
    return a;
}
__device__ __forceinline__ void ldm4(uint32_t* r, uint32_t addr) {
    asm volatile("ldmatrix.sync.aligned.m8n8.x4.shared.b16 {%0,%1,%2,%3}, [%4];"
                 : "=r"(r[0]), "=r"(r[1]), "=r"(r[2]), "=r"(r[3]) : "r"(addr));
}
__device__ __forceinline__ void mma16816(float* d, const uint32_t* a, const uint32_t* b) {
    asm volatile(
        "mma.sync.aligned.m16n8k16.row.col.f32.f16.f16.f32 "
        "{%0,%1,%2,%3}, {%4,%5,%6,%7}, {%8,%9}, {%0,%1,%2,%3};"
        : "+f"(d[0]), "+f"(d[1]), "+f"(d[2]), "+f"(d[3])
        : "r"(a[0]), "r"(a[1]), "r"(a[2]), "r"(a[3]), "r"(b[0]), "r"(b[1]));
}
__device__ __forceinline__ uint32_t pack_h2(float a, float b) {
    __half2 t = __floats2half2_rn(a, b);
    return *(uint32_t*)&t;
}

// ---------------- prep: zero state + weight fusion + fp16 cast -----------------
__global__ void prep_k(const float* __restrict__ W, const float* __restrict__ Wih,
                       const float* __restrict__ Whh, float* __restrict__ out) {
    int tid = blockIdx.x * blockDim.x + threadIdx.x;
    if (tid < NN) g_cnt[tid] = 0;
    if (tid < SCAN_BLKS) g_flag[tid] = 0;
    if (tid < NG * HD) out[tid] = 0.f;
    if (tid < NLAY * G3 * HD) {
        int c = tid & (HD - 1);
        int j = (tid >> 6) % G3;
        int l = tid / (G3 * HD);
        const float* wrow = W + (l * HD + c) * HD;
        const float* irow = Wih + j * HD;
        float s = 0.f;
#pragma unroll
        for (int k = 0; k < HD; k++) s = fmaf(wrow[k], irow[k], s);
        g_wf[tid] = __float2half(s);
    }
    if (tid < G3 * HD) g_wh[tid] = __float2half(Whh[tid]);
}

// ---------------- CSR build ----------------------------------------------------
__global__ void hist_k(const int* __restrict__ dst) {
    int e = blockIdx.x * blockDim.x + threadIdx.x;
    if (e < NE) atomicAdd(&g_cnt[dst[e]], 1);
}

// single-pass decoupled-lookback scan (196 blocks, all resident)
__global__ void scan_k() {
    __shared__ int ss[SCAN_TPB];
    __shared__ int s_excl;
    int t = threadIdx.x, b = blockIdx.x;
    int i = b * SCAN_TPB + t;
    int orig = (i < NN) ? g_cnt[i] : 0;
    ss[t] = orig;
    __syncthreads();
#pragma unroll
    for (int off = 1; off < SCAN_TPB; off <<= 1) {
        int u = (t >= off) ? ss[t - off] : 0;
        __syncthreads();
        ss[t] += u;
        __syncthreads();
    }
    int incl = ss[t];
    int total = ss[SCAN_TPB - 1];

    if (t == 0) {
        if (b == 0) {
            *(volatile int*)&g_incv[0] = total;
            __threadfence();
            *(volatile int*)&g_flag[0] = 2;
            s_excl = 0;
        } else {
            *(volatile int*)&g_aggv[b] = total;
            __threadfence();
            *(volatile int*)&g_flag[b] = 1;
        }
    }
    if (b > 0 && t < 32) {
        int running = 0;
        for (int base = b - 1; base >= 0; base -= 32) {
            int idx = base - t;
            int f;
            do {
                f = (idx >= 0) ? *(volatile int*)&g_flag[idx] : 2;
            } while (__any_sync(0xffffffffu, f == 0));
            __threadfence();
            int val = 0;
            if (idx >= 0)
                val = (f == 2) ? *(volatile int*)&g_incv[idx] : *(volatile int*)&g_aggv[idx];
            unsigned m = __ballot_sync(0xffffffffu, (f == 2) && idx >= 0);
            int firstP = m ? (__ffs(m) - 1) : 32;
            int contrib = (t <= firstP && idx >= 0) ? val : 0;
#pragma unroll
            for (int o = 16; o; o >>= 1) contrib += __shfl_down_sync(0xffffffffu, contrib, o);
            contrib = __shfl_sync(0xffffffffu, contrib, 0);
            running += contrib;
            if (m) break;
        }
        if (t == 0) {
            *(volatile int*)&g_incv[b] = running + total;
            __threadfence();
            *(volatile int*)&g_flag[b] = 2;
            s_excl = running;
        }
    }
    __syncthreads();
    int excl = s_excl + incl - orig;
    if (i < NN) {
        g_rowptr[i] = excl;
        g_cnt[i] = excl;   // scatter cursor
    }
    if (i == 0) g_rowptr[NN] = NE;
}

__global__ void scatter_k(const int* __restrict__ src, const int* __restrict__ dst) {
    int e = blockIdx.x * blockDim.x + threadIdx.x;
    if (e < NE) {
        int p = atomicAdd(&g_cnt[dst[e]], 1);
        g_col[p] = src[e];
    }
}

// ---------------- aggregation: one warp per node, float2 per lane --------------
__global__ void agg_k(const float2* __restrict__ h2, float2* __restrict__ out2) {
    int w    = (blockIdx.x * blockDim.x + threadIdx.x) >> 5;
    int lane = threadIdx.x & 31;
    if (w >= NN) return;
    int beg = g_rowptr[w], end = g_rowptr[w + 1];
    float2 acc = make_float2(0.f, 0.f);
    for (int base = beg; base < end; base += 32) {
        int m = min(32, end - base);
        int idx = 0;
        if (lane < m) idx = g_col[base + lane];
#pragma unroll 4
        for (int jj = 0; jj < m; jj++) {
            int s = __shfl_sync(0xffffffffu, idx, jj);
            float2 v = h2[s * 32 + lane];
            acc.x += v.x;
            acc.y += v.y;
        }
    }
    out2[w * 32 + lane] = acc;
}

// ---------------- GRU via single-product fp16 mma.sync, 2 blocks/SM ------------
// SMEM: A 9216 + H 9216 + Wf 27648 + Wh 27648 = 73728 bytes (x2 blocks = 147KB)
#define ROWB 144
#define OFF_A  0
#define OFF_H  9216
#define OFF_WF 18432
#define OFF_WH 46080
#define GRU_SMEM 73728
#define NTILES ((NN + 63) / 64)   // 1563
#define GRU_GRID 296
#define GRU_TPB 256

#define IDX(p, t, h) ((((p) * 2 + (t)) * 2 + (h)) * 4)

__global__ void __launch_bounds__(GRU_TPB, 2) gru_mma(
    const float* __restrict__ agg, const float* __restrict__ hin,
    float* __restrict__ hout,
    const __half* __restrict__ wf,
    const float* __restrict__ bih, const float* __restrict__ bhh) {
    extern __shared__ __align__(16) char sm[];
    int tid = threadIdx.x, wid = tid >> 5, lane = tid & 31;

    // ---- stage weights ONCE (fp16, [gate][c] rows) ----
    for (int i = tid; i < G3 * 16; i += GRU_TPB) {
        int r = i >> 4, c8 = i & 15;
        uint32_t off = r * ROWB + c8 * 8;
        *(uint2*)(sm + OFF_WF + off) = *(const uint2*)(wf + r * 64 + c8 * 4);
        *(uint2*)(sm + OFF_WH + off) = *(const uint2*)(g_wh + r * 64 + c8 * 4);
    }

    uint32_t sbase = smem_u32(sm);
    int mrow0 = (wid & 3) * 16;        // 4 M-stripes of 16 rows
    int d0 = (wid >> 2) * 32;          // 2 feature groups of 32
    uint32_t aOff = (mrow0 + (lane & 15)) * ROWB + (lane >> 4) * 16;
    uint32_t bRow = (lane >> 4) * 8 + (lane & 7);
    uint32_t bCol = ((lane >> 3) & 1) * 16;

    for (int tile = blockIdx.x; tile < NTILES; tile += GRU_GRID) {
        int n0 = tile * 64;
        __syncthreads();   // previous tile's MMA readers done

        // ---- stage A/H (fp32 -> fp16) ----
        for (int i = tid; i < 64 * 16; i += GRU_TPB) {
            int t = i >> 4, c4 = i & 15;
            float4 a = make_float4(0.f, 0.f, 0.f, 0.f), h = a;
            if (n0 + t < NN) {
                a = ((const float4*)(agg + (size_t)(n0 + t) * HD))[c4];
                h = ((const float4*)(hin + (size_t)(n0 + t) * HD))[c4];
            }
            uint32_t off = t * ROWB + c4 * 8;
            *(uint2*)(sm + OFF_A + off) =
                make_uint2(pack_h2(a.x, a.y), pack_h2(a.z, a.w));
            *(uint2*)(sm + OFF_H + off) =
                make_uint2(pack_h2(h.x, h.y), pack_h2(h.z, h.w));
        }
        __syncthreads();

        // ---- single-product fp16 GEMMs: 3 gate planes x 2 n16 groups ----
        float dgi[48], dgh[48];
#pragma unroll
        for (int q = 0; q < 48; q++) { dgi[q] = 0.f; dgh[q] = 0.f; }

#pragma unroll
        for (int ks = 0; ks < 4; ks++) {
            uint32_t kb = ks * 32;
            uint32_t aF[4], hF[4];
            ldm4(aF, sbase + OFF_A + aOff + kb);
            ldm4(hF, sbase + OFF_H + aOff + kb);
#pragma unroll
            for (int p = 0; p < 3; p++) {
#pragma unroll
                for (int t = 0; t < 2; t++) {
                    uint32_t bo = (p * 64 + d0 + t * 16 + bRow) * ROWB + bCol + kb;
                    int I = IDX(p, t, 0);
                    uint32_t bF[4], bG[4];
                    ldm4(bF, sbase + OFF_WF + bo);
                    ldm4(bG, sbase + OFF_WH + bo);
                    mma16816(dgi + I,     aF, bF);
                    mma16816(dgi + I + 4, aF, bF + 2);
                    mma16816(dgh + I,     hF, bG);
                    mma16816(dgh + I + 4, hF, bG + 2);
                }
            }
        }

        // ---- register epilogue: biases + h_prev loaded here (L1/L2-hot),
        //      latency hidden by the co-resident block's MMA phase ----
#pragma unroll
        for (int t = 0; t < 2; t++)
#pragma unroll
            for (int h = 0; h < 2; h++) {
                int dE = d0 + t * 16 + h * 8 + (lane & 3) * 2;
                float2 bi_r = *(const float2*)(bih + dE);
                float2 bh_r = *(const float2*)(bhh + dE);
                float2 bi_z = *(const float2*)(bih + 64 + dE);
                float2 bh_z = *(const float2*)(bhh + 64 + dE);
                float2 bi_n = *(const float2*)(bih + 128 + dE);
                float2 bh_n = *(const float2*)(bhh + 128 + dE);
                float brz[2] = {bi_r.x + bh_r.x, bi_r.y + bh_r.y};
                float bzz[2] = {bi_z.x + bh_z.x, bi_z.y + bh_z.y};
                float bnn[2] = {bi_n.x, bi_n.y};
                float bhn[2] = {bh_n.x, bh_n.y};
#pragma unroll
                for (int rh = 0; rh < 2; rh++) {
                    int row = mrow0 + (lane >> 2) + rh * 8;
                    if (n0 + row >= NN) continue;
                    float2 hpv = *(const float2*)(hin + (size_t)(n0 + row) * HD + dE);
                    float hpa[2] = {hpv.x, hpv.y};
                    float outv[2];
#pragma unroll
                    for (int j = 0; j < 2; j++) {
                        int q = rh * 2 + j;
                        float ar = dgi[IDX(0, t, h) + q] + dgh[IDX(0, t, h) + q] + brz[j];
                        float az = dgi[IDX(1, t, h) + q] + dgh[IDX(1, t, h) + q] + bzz[j];
                        float r = 1.f / (1.f + __expf(-ar));
                        float z = 1.f / (1.f + __expf(-az));
                        float xarg = dgi[IDX(2, t, h) + q] + bnn[j] +
                                     r * (dgh[IDX(2, t, h) + q] + bhn[j]);
                        float nn = 1.f - 2.f / (__expf(2.f * xarg) + 1.f);  // tanh
                        outv[j] = (1.f - z) * nn + z * hpa[j];
                    }
                    *(float2*)(hout + (size_t)(n0 + row) * HD + dE) =
                        make_float2(outv[0], outv[1]);
                }
            }
    }
}

// ---------------- pooling: batch sorted -> run-length accumulate ---------------
__global__ void pool_k(const float* __restrict__ h, const int* __restrict__ batch,
                       float* __restrict__ out) {
    int d = threadIdx.x;
    int n0 = blockIdx.x * 128;
    int nend = min(n0 + 128, NN);
    if (n0 >= NN) return;
    float acc = 0.f;
    int cur = batch[n0];
    for (int n = n0; n < nend; n++) {
        int b = batch[n];
        if (b != cur) {
            atomicAdd(&out[cur * HD + d], acc);
            acc = 0.f;
            cur = b;
        }
        acc += h[(size_t)n * HD + d];
    }
    atomicAdd(&out[cur * HD + d], acc);
}

// ---------------- launch --------------------------------------------------------
extern "C" void kernel_launch(void* const* d_in, const int* in_sizes, int n_in,
                              void* d_out, int out_size) {
    const float* x    = (const float*)d_in[0];
    const int*   ei   = (const int*)d_in[1];
    const int*   batch= (const int*)d_in[2];
    const float* W    = (const float*)d_in[3];
    const float* Wih  = (const float*)d_in[4];
    const float* Whh  = (const float*)d_in[5];
    const float* bih  = (const float*)d_in[6];
    const float* bhh  = (const float*)d_in[7];
    float* out = (float*)d_out;
    const int* src = ei;
    const int* dst = ei + NE;

    void *h0p, *h1p, *aggp, *wfp;
    cudaGetSymbolAddress(&h0p, g_h0);
    cudaGetSymbolAddress(&h1p, g_h1);
    cudaGetSymbolAddress(&aggp, g_agg);
    cudaGetSymbolAddress(&wfp, g_wf);

    cudaFuncSetAttribute(gru_mma, cudaFuncAttributeMaxDynamicSharedMemorySize, GRU_SMEM);

    prep_k<<<(NN + 255) / 256, 256>>>(W, Wih, Whh, out);
    hist_k<<<(NE + 255) / 256, 256>>>(dst);
    scan_k<<<SCAN_BLKS, SCAN_TPB>>>();
    scatter_k<<<(NE + 255) / 256, 256>>>(src, dst);

    const float* hin = x;
    for (int l = 0; l < NLAY; l++) {
        float* hout = (l & 1) ? (float*)h0p : (float*)h1p;
        agg_k<<<(NN * 32) / 256, 256>>>((const float2*)hin, (float2*)aggp);
        gru_mma<<<GRU_GRID, GRU_TPB, GRU_SMEM>>>(
            (const float*)aggp, hin, hout,
            (const __half*)wfp + (size_t)l * G3 * HD,
            bih, bhh);
        hin = hout;
    }
    pool_k<<<(NN + 127) / 128, 64>>>(hin, batch, out);
}